// round 1
// baseline (speedup 1.0000x reference)
#include <cuda_runtime.h>
#include <math.h>

#define B_    8
#define C_    256
#define HW_   9216
#define HEADS 8
#define CH    32      // channels per head
#define SPLITS 8      // p-splits for S accumulation

// ---------------- scratch (static __device__ — no allocation) ----------------
__device__ float g_q[B_ * C_ * HW_];
__device__ float g_k[B_ * C_ * HW_];
__device__ float g_v[B_ * C_ * HW_];
__device__ float g_Wqx[C_ * C_];
__device__ float g_Wqy[C_ * C_];
__device__ float g_bq[C_];
__device__ float g_inv_q[B_ * C_];
__device__ float g_inv_k[B_ * C_];
__device__ float g_Spart[B_ * HEADS * SPLITS * CH * CH];
__device__ float g_A[B_ * HEADS * CH * CH];
__device__ float g_Mf[B_ * C_ * C_];

// ---------------- kernel 1: fold q weights ----------------
// Wqx = W_cat[:, :128] @ W_qr ;  Wqy = W_cat[:, 128:] @ W_qd
// bq  = W_cat @ [b_qr; b_qd] + b_cat
__global__ void fold_weights(const float* __restrict__ Wcat,
                             const float* __restrict__ Wqr,
                             const float* __restrict__ Wqd,
                             const float* __restrict__ bqr,
                             const float* __restrict__ bqd,
                             const float* __restrict__ bcat) {
    int o  = blockIdx.x;   // 0..255 output channel
    int ci = threadIdx.x;  // 0..255 input channel
    float sx = 0.f, sy = 0.f;
    #pragma unroll 8
    for (int j = 0; j < 128; j++) {
        float wl = Wcat[o * 256 + j];
        float wr = Wcat[o * 256 + 128 + j];
        sx += wl * Wqr[j * 256 + ci];
        sy += wr * Wqd[j * 256 + ci];
    }
    g_Wqx[o * 256 + ci] = sx;
    g_Wqy[o * 256 + ci] = sy;
    if (ci == 0) {
        float s = bcat[o];
        for (int j = 0; j < 128; j++)
            s += Wcat[o * 256 + j] * bqr[j] + Wcat[o * 256 + 128 + j] * bqd[j];
        g_bq[o] = s;
    }
}

// ---------------- kernel 2: SGEMM 128x128x8, 8x8 microtile ----------------
// out[b, m, n] = sum_k W[m,k] * X1[b,k,n]  (+ sum_k W2[m,k] * X2[b,k,n] if X2)
//               + bias[m] (+ res[b,m,n] if res)
// W row-stride = 256 always. N = HW_ = 9216 always. M covered by blockIdx.y*128.
__global__ void __launch_bounds__(256, 2)
sgemm128(const float* __restrict__ W1, const float* __restrict__ X1,
         const float* __restrict__ W2, const float* __restrict__ X2,
         const float* __restrict__ bias, const float* __restrict__ res,
         float* __restrict__ out, long wStride)
{
    __shared__ float Ws[8][132];
    __shared__ float Xs[8][128];

    const int tid = threadIdx.x;
    const int bz  = blockIdx.z;
    const long xoff = (long)bz * ((long)C_ * HW_);
    const float* Wa = W1 + (long)bz * wStride;
    const float* XA = X1 + xoff;
    const float* XB = X2 ? (X2 + xoff) : (const float*)0;

    const int row0 = blockIdx.y * 128;
    const int col0 = blockIdx.x * 128;

    const int wRow = tid >> 1;
    const int wCol = (tid & 1) * 4;
    const int xRow = tid >> 5;
    const int xCol = (tid & 31) * 4;

    const int ntiles = X2 ? 64 : 32;   // (K_total / 8)

    // prefetch tile 0 (always part 0)
    float4 wv = *(const float4*)&Wa[(long)(row0 + wRow) * 256 + wCol];
    float4 xv = *(const float4*)&XA[(long)xRow * HW_ + col0 + xCol];

    float acc[8][8] = {};

    const int ry = (tid >> 4) * 8;
    const int cx = (tid & 15) * 8;

    for (int kt = 0; kt < ntiles; kt++) {
        Ws[wCol + 0][wRow] = wv.x;
        Ws[wCol + 1][wRow] = wv.y;
        Ws[wCol + 2][wRow] = wv.z;
        Ws[wCol + 3][wRow] = wv.w;
        *(float4*)&Xs[xRow][xCol] = xv;
        __syncthreads();

        if (kt + 1 < ntiles) {
            int kn = (kt + 1) << 3;
            const float* W; const float* X; int kk;
            if (kn >= 256) { W = W2; X = XB; kk = kn - 256; }
            else           { W = Wa; X = XA; kk = kn; }
            wv = *(const float4*)&W[(long)(row0 + wRow) * 256 + kk + wCol];
            xv = *(const float4*)&X[(long)(kk + xRow) * HW_ + col0 + xCol];
        }

        #pragma unroll
        for (int k = 0; k < 8; k++) {
            float a[8], bb[8];
            *(float4*)&a[0]  = *(const float4*)&Ws[k][ry];
            *(float4*)&a[4]  = *(const float4*)&Ws[k][ry + 4];
            *(float4*)&bb[0] = *(const float4*)&Xs[k][cx];
            *(float4*)&bb[4] = *(const float4*)&Xs[k][cx + 4];
            #pragma unroll
            for (int i = 0; i < 8; i++)
                #pragma unroll
                for (int j = 0; j < 8; j++)
                    acc[i][j] = fmaf(a[i], bb[j], acc[i][j]);
        }
        __syncthreads();
    }

    // epilogue
    #pragma unroll
    for (int i = 0; i < 8; i++) {
        int r = row0 + ry + i;
        float bv = bias[r];
        long base = xoff + (long)r * HW_ + col0 + cx;
        #pragma unroll
        for (int j = 0; j < 8; j += 4) {
            float4 o;
            o.x = acc[i][j + 0] + bv;
            o.y = acc[i][j + 1] + bv;
            o.z = acc[i][j + 2] + bv;
            o.w = acc[i][j + 3] + bv;
            if (res) {
                float4 rv = *(const float4*)&res[base + j];
                o.x += rv.x; o.y += rv.y; o.z += rv.z; o.w += rv.w;
            }
            *(float4*)&out[base + j] = o;
        }
    }
}

// ---------------- kernel 3: inverse L2 norms of q and k ----------------
// grid (C_, B_, 2), block 256
__global__ void norm_kernel() {
    const float* src = blockIdx.z ? g_k : g_q;
    float* dst       = blockIdx.z ? g_inv_k : g_inv_q;
    const float* p = src + ((long)blockIdx.y * C_ + blockIdx.x) * HW_;
    int tid = threadIdx.x;
    float ss = 0.f;
    for (int i = tid * 4; i < HW_; i += 1024) {
        float4 v = *(const float4*)&p[i];
        ss += v.x * v.x + v.y * v.y + v.z * v.z + v.w * v.w;
    }
    #pragma unroll
    for (int o = 16; o; o >>= 1) ss += __shfl_xor_sync(0xffffffffu, ss, o);
    __shared__ float red[8];
    if ((tid & 31) == 0) red[tid >> 5] = ss;
    __syncthreads();
    if (tid < 8) {
        float v = red[tid];
        #pragma unroll
        for (int o = 4; o; o >>= 1) v += __shfl_xor_sync(0xffu, v, o);
        if (tid == 0)
            dst[blockIdx.y * C_ + blockIdx.x] = 1.f / fmaxf(sqrtf(v), 1e-12f);
    }
}

// ---------------- kernel 4: partial S = q_raw . k_raw^T ----------------
// grid (HEADS, B_, SPLITS), block 64. 4x4 microtile per thread.
__global__ void attn_s_kernel() {
    int h = blockIdx.x, b = blockIdx.y, sp = blockIdx.z;
    const float* qb = g_q + ((long)b * C_ + h * CH) * HW_;
    const float* kb = g_k + ((long)b * C_ + h * CH) * HW_;
    const int PLEN = HW_ / SPLITS;   // 1152
    int p0 = sp * PLEN;

    __shared__ float Qs[64][32];
    __shared__ float Ks[64][32];

    int tid = threadIdx.x;
    int lc = tid & 31;           // loader channel
    int lp = (tid >> 5) * 4;     // loader p sub-offset (0 or 4)
    int cg = (tid >> 3) * 4;     // compute c group
    int dg = (tid & 7) * 4;      // compute d group

    float acc[4][4] = {};

    for (int pt = 0; pt < PLEN; pt += 64) {
        #pragma unroll
        for (int pp = 0; pp < 64; pp += 8) {
            long goff = (long)lc * HW_ + p0 + pt + pp + lp;
            float4 qv = *(const float4*)&qb[goff];
            float4 kv = *(const float4*)&kb[goff];
            Qs[pp + lp + 0][lc] = qv.x; Qs[pp + lp + 1][lc] = qv.y;
            Qs[pp + lp + 2][lc] = qv.z; Qs[pp + lp + 3][lc] = qv.w;
            Ks[pp + lp + 0][lc] = kv.x; Ks[pp + lp + 1][lc] = kv.y;
            Ks[pp + lp + 2][lc] = kv.z; Ks[pp + lp + 3][lc] = kv.w;
        }
        __syncthreads();
        #pragma unroll 4
        for (int p = 0; p < 64; p++) {
            float a[4], bb[4];
            #pragma unroll
            for (int i = 0; i < 4; i++) a[i]  = Qs[p][cg + i];
            #pragma unroll
            for (int j = 0; j < 4; j++) bb[j] = Ks[p][dg + j];
            #pragma unroll
            for (int i = 0; i < 4; i++)
                #pragma unroll
                for (int j = 0; j < 4; j++)
                    acc[i][j] = fmaf(a[i], bb[j], acc[i][j]);
        }
        __syncthreads();
    }

    float* Sp = g_Spart + ((long)(b * HEADS + h) * SPLITS + sp) * (CH * CH);
    #pragma unroll
    for (int i = 0; i < 4; i++)
        #pragma unroll
        for (int j = 0; j < 4; j++)
            Sp[(cg + i) * CH + dg + j] = acc[i][j];
}

// ---------------- kernel 5: reduce splits, scale, softmax ----------------
// grid (B_*HEADS), block 32 (thread = row c)
__global__ void softmax_kernel(const float* __restrict__ temp) {
    int bh = blockIdx.x;
    int b = bh / HEADS, h = bh % HEADS;
    int c = threadIdx.x;
    float iq = g_inv_q[b * C_ + h * CH + c];
    float t  = temp[h];
    float row[CH];
    float mx = -1e30f;
    #pragma unroll
    for (int d = 0; d < CH; d++) {
        float s = 0.f;
        #pragma unroll
        for (int sp = 0; sp < SPLITS; sp++)
            s += g_Spart[((long)bh * SPLITS + sp) * (CH * CH) + c * CH + d];
        s *= iq * g_inv_k[b * C_ + h * CH + d] * t;
        row[d] = s;
        mx = fmaxf(mx, s);
    }
    float sum = 0.f;
    #pragma unroll
    for (int d = 0; d < CH; d++) { row[d] = expf(row[d] - mx); sum += row[d]; }
    float inv = 1.f / sum;
    #pragma unroll
    for (int d = 0; d < CH; d++)
        g_A[(long)bh * (CH * CH) + c * CH + d] = row[d] * inv;
}

// ---------------- kernel 6: Mf[b] = W_proj @ blockdiag(A[b]) ----------------
// grid (HEADS, B_), block 256 (thread = output channel c)
__global__ void mfuse_kernel(const float* __restrict__ Wproj) {
    int h = blockIdx.x, b = blockIdx.y;
    __shared__ float As[CH][CH + 1];
    int tid = threadIdx.x;
    for (int i = tid; i < CH * CH; i += 256)
        As[i >> 5][i & 31] = g_A[(long)(b * HEADS + h) * (CH * CH) + i];
    __syncthreads();
    int c = tid;
    float w[CH];
    #pragma unroll
    for (int e = 0; e < CH; e++) w[e] = Wproj[c * 256 + h * CH + e];
    #pragma unroll 4
    for (int d = 0; d < CH; d++) {
        float s = 0.f;
        #pragma unroll
        for (int e = 0; e < CH; e++) s = fmaf(w[e], As[e][d], s);
        g_Mf[((long)b * C_ + c) * C_ + h * CH + d] = s;
    }
}

// ---------------- launch ----------------
extern "C" void kernel_launch(void* const* d_in, const int* in_sizes, int n_in,
                              void* d_out, int out_size) {
    const float* x      = (const float*)d_in[0];
    const float* y      = (const float*)d_in[1];
    const float* z      = (const float*)d_in[2];
    const float* W_qr   = (const float*)d_in[3];
    const float* b_qr   = (const float*)d_in[4];
    const float* W_qd   = (const float*)d_in[5];
    const float* b_qd   = (const float*)d_in[6];
    const float* W_kf   = (const float*)d_in[7];
    const float* b_kf   = (const float*)d_in[8];
    const float* W_vf   = (const float*)d_in[9];
    const float* b_vf   = (const float*)d_in[10];
    const float* W_cat  = (const float*)d_in[11];
    const float* b_cat  = (const float*)d_in[12];
    const float* W_proj = (const float*)d_in[13];
    const float* b_proj = (const float*)d_in[14];
    const float* temp   = (const float*)d_in[15];
    float* out = (float*)d_out;

    float *p_q, *p_k, *p_v, *p_Wqx, *p_Wqy, *p_bq, *p_Mf;
    cudaGetSymbolAddress((void**)&p_q,   g_q);
    cudaGetSymbolAddress((void**)&p_k,   g_k);
    cudaGetSymbolAddress((void**)&p_v,   g_v);
    cudaGetSymbolAddress((void**)&p_Wqx, g_Wqx);
    cudaGetSymbolAddress((void**)&p_Wqy, g_Wqy);
    cudaGetSymbolAddress((void**)&p_bq,  g_bq);
    cudaGetSymbolAddress((void**)&p_Mf,  g_Mf);

    fold_weights<<<256, 256>>>(W_cat, W_qr, W_qd, b_qr, b_qd, b_cat);

    dim3 gg(HW_ / 128, C_ / 128, B_);   // (72, 2, 8)
    // q = Wqx@x + Wqy@y + bq
    sgemm128<<<gg, 256>>>(p_Wqx, x, p_Wqy, y, p_bq, nullptr, p_q, 0);
    // k = W_kf@z + b_kf ;  v = W_vf@z + b_vf
    sgemm128<<<gg, 256>>>(W_kf, z, nullptr, nullptr, b_kf, nullptr, p_k, 0);
    sgemm128<<<gg, 256>>>(W_vf, z, nullptr, nullptr, b_vf, nullptr, p_v, 0);

    norm_kernel<<<dim3(C_, B_, 2), 256>>>();
    attn_s_kernel<<<dim3(HEADS, B_, SPLITS), 64>>>();
    softmax_kernel<<<B_ * HEADS, 32>>>(temp);
    mfuse_kernel<<<dim3(HEADS, B_), 256>>>(W_proj);

    // final: out = Mf[b] @ v + b_proj + z
    sgemm128<<<gg, 256>>>(p_Mf, p_v, nullptr, nullptr, b_proj, z, out, (long)C_ * C_);
}